// round 5
// baseline (speedup 1.0000x reference)
#include <cuda_runtime.h>
#include <cstdint>

// ChamferLoss: B=8, N=M=4096, C=3, fp32 in, scalar fp32 out.
// dist2(s,t) = |s|^2 + |t|^2 - 2 s.t ;  min_t dist2 = |s|^2 - 2 * max_t (s.t - |t|^2/2)
// Inner loop: packed fma.rn.f32x2 -> 3 FFMA2 + 2 FMNMX per (2 rows x 1 target).

#define BATCH     8
#define NPTS      4096
#define BN        (BATCH * NPTS)     // 32768 points per cloud
#define THREADS   128
#define ROWS      8                  // source rows per thread
#define PAIRS     (ROWS / 2)         // packed f32x2 row-pairs
#define TN        (THREADS * ROWS)   // 1024 sources per block
#define NX        (NPTS / TN)        // 4
#define NM_CHUNKS 16
#define MCHUNK    (NPTS / NM_CHUNKS) // 256 targets per block, single shared tile

#define S2_BLOCKS  128
#define S2_THREADS 64
#define GROUPS     (BN / 4)          // 8192 float4 point-groups

// Partial maxima: [dir][m-chunk][b*NPTS + i]. Every slot written every run.
__device__ float g_part[2][NM_CHUNKS][BN];
__device__ float g_bsum[S2_BLOCKS];
__device__ int   g_count;  // statically 0; last block resets it for graph replay

typedef unsigned long long ull;

__device__ __forceinline__ ull pk2(float a, float b) {
    ull r;
    asm("mov.b64 %0, {%1, %2};" : "=l"(r) : "f"(a), "f"(b));
    return r;
}
__device__ __forceinline__ void upk2(ull v, float& lo, float& hi) {
    asm("mov.b64 {%0, %1}, %2;" : "=f"(lo), "=f"(hi) : "l"(v));
}
__device__ __forceinline__ ull fma2(ull a, ull b, ull c) {
    ull r;
    asm("fma.rn.f32x2 %0, %1, %2, %3;" : "=l"(r) : "l"(a), "l"(b), "l"(c));
    return r;
}

// Both directions in one launch: blockIdx.z in [0,16); dir = z/8, b = z%8.
__global__ __launch_bounds__(THREADS, 7)
void dir_max_kernel(const float* __restrict__ f, const float* __restrict__ f_) {
    const int z   = blockIdx.z;
    const int dir = z >> 3;
    const int b   = z & 7;
    const float* src = dir ? f_ : f;
    const float* tgt = dir ? f  : f_;

    const int n0 = blockIdx.x * TN;
    const int mc = blockIdx.y;
    const int t  = threadIdx.x;

    // Targets pre-duplicated for packed math:
    // sh_xy[j] = { {x,x}, {y,y} },  sh_zw[j] = { {z,z}, {w,w} }, w = -|t|^2/2
    __shared__ ulonglong2 sh_xy[MCHUNK];
    __shared__ ulonglong2 sh_zw[MCHUNK];
    __shared__ float      sh_src[TN * 3];  // 12 KB staged source rows

    // Coalesced cooperative source stage: TN*3 floats = 768 float4 (16B-aligned:
    // (b*4096+n0)*3*4B is a multiple of 12288).
    {
        const float4* s4 = (const float4*)(src + ((size_t)b * NPTS + n0) * 3);
        float4* d4 = (float4*)sh_src;
#pragma unroll
        for (int k = 0; k < (TN * 3) / (4 * THREADS); k++)  // 6
            d4[t + k * THREADS] = s4[t + k * THREADS];
    }

    // Target tile: 2 targets per thread, precompute duplicated packed form.
#pragma unroll
    for (int k = 0; k < MCHUNK / THREADS; k++) {  // 2
        int j = t + k * THREADS;
        const float* q = tgt + ((size_t)b * NPTS + mc * MCHUNK + j) * 3;
        float x = q[0], y = q[1], zz = q[2];
        float w = -0.5f * (x * x + y * y + zz * zz);
        sh_xy[j] = make_ulonglong2(pk2(x, x), pk2(y, y));
        sh_zw[j] = make_ulonglong2(pk2(zz, zz), pk2(w, w));
    }
    __syncthreads();  // the only barrier

    // Pick 8 source rows from shared (stride-3 banks: conflict-free), pack.
    ull sx2[PAIRS], sy2[PAIRS], sz2[PAIRS];
    float mx[ROWS];
#pragma unroll
    for (int p = 0; p < PAIRS; p++) {
        int i0 = (t + (2 * p)     * THREADS) * 3;
        int i1 = (t + (2 * p + 1) * THREADS) * 3;
        sx2[p] = pk2(sh_src[i0 + 0], sh_src[i1 + 0]);
        sy2[p] = pk2(sh_src[i0 + 1], sh_src[i1 + 1]);
        sz2[p] = pk2(sh_src[i0 + 2], sh_src[i1 + 2]);
        mx[2 * p] = -3.402823466e+38f;
        mx[2 * p + 1] = -3.402823466e+38f;
    }

    // Mainloop: explicit register double-buffer of the target (wraparound index
    // avoids a tail branch; the AND folds under unroll).
    ulonglong2 xy = sh_xy[0];
    ulonglong2 zw = sh_zw[0];
#pragma unroll 8
    for (int j = 0; j < MCHUNK; j++) {
        const int jn = (j + 1) & (MCHUNK - 1);
        ulonglong2 xy_n = sh_xy[jn];  // prefetch next target
        ulonglong2 zw_n = sh_zw[jn];
#pragma unroll
        for (int p = 0; p < PAIRS; p++) {
            ull v = fma2(sx2[p], xy.x, zw.y);   // s.x*t.x + w
            v = fma2(sy2[p], xy.y, v);
            v = fma2(sz2[p], zw.x, v);
            float v0, v1;
            upk2(v, v0, v1);                    // register-pair halves
            mx[2 * p]     = fmaxf(mx[2 * p],     v0);
            mx[2 * p + 1] = fmaxf(mx[2 * p + 1], v1);
        }
        xy = xy_n; zw = zw_n;
    }

#pragma unroll
    for (int r = 0; r < ROWS; r++) {
        int i = n0 + t + r * THREADS;
        g_part[dir][mc][b * NPTS + i] = mx[r];  // dense unique slot, no atomics
    }
}

__device__ __forceinline__ float4 max4(float4 a, float4 b) {
    return make_float4(fmaxf(a.x, b.x), fmaxf(a.y, b.y),
                       fmaxf(a.z, b.z), fmaxf(a.w, b.w));
}

// Per-direction contribution for one float4-group (4 points) of one direction.
__device__ __forceinline__ float group_term(const float* __restrict__ pts,
                                            const float* __restrict__ part_base,
                                            int g) {
    float4 m = ((const float4*)part_base)[g];
#pragma unroll
    for (int c = 1; c < NM_CHUNKS; c++)
        m = max4(m, ((const float4*)(part_base + (size_t)c * BN))[g]);

    const float4* fv = (const float4*)pts;
    float4 a = fv[3 * g], b4 = fv[3 * g + 1], c4 = fv[3 * g + 2];
    float n0 = a.x * a.x + a.y * a.y + a.z * a.z;
    float n1 = a.w * a.w + b4.x * b4.x + b4.y * b4.y;
    float n2 = b4.z * b4.z + b4.w * b4.w + c4.x * c4.x;
    float n3 = c4.y * c4.y + c4.z * c4.z + c4.w * c4.w;
    return (n0 - 2.0f * m.x) + (n1 - 2.0f * m.y)
         + (n2 - 2.0f * m.z) + (n3 - 2.0f * m.w);
}

// Fused stage 2: one float4-group per thread, vectorized loads, last block
// (threadfence-reduction) does the deterministic final tree.
__global__ __launch_bounds__(S2_THREADS)
void stage2_kernel(const float* __restrict__ f, const float* __restrict__ f_,
                   float* __restrict__ out) {
    const int tid = threadIdx.x;
    const int g = blockIdx.x * S2_THREADS + tid;  // exactly GROUPS threads

    float acc = group_term(f,  &g_part[0][0][0], g)
              + group_term(f_, &g_part[1][0][0], g);

    __shared__ float red[S2_THREADS];
    __shared__ bool last;
    red[tid] = acc;
    __syncthreads();
#pragma unroll
    for (int s = S2_THREADS / 2; s > 0; s >>= 1) {
        if (tid < s) red[tid] += red[tid + s];
        __syncthreads();
    }
    if (tid == 0) {
        g_bsum[blockIdx.x] = red[0];
        __threadfence();
        last = (atomicAdd(&g_count, 1) == S2_BLOCKS - 1);
    }
    __syncthreads();

    if (last) {
        __threadfence();  // acquire: all g_bsum writes visible
        red[tid] = g_bsum[tid] + g_bsum[tid + S2_THREADS];  // 128 -> 64
        __syncthreads();
#pragma unroll
        for (int s = S2_THREADS / 2; s > 0; s >>= 1) {
            if (tid < s) red[tid] += red[tid + s];
            __syncthreads();
        }
        if (tid == 0) {
            out[0] = red[0] * (1.0f / (float)BN);
            g_count = 0;  // reset for next graph replay
        }
    }
}

extern "C" void kernel_launch(void* const* d_in, const int* in_sizes, int n_in,
                              void* d_out, int out_size) {
    const float* f  = (const float*)d_in[0];
    const float* f_ = (const float*)d_in[1];
    float* out = (float*)d_out;

    dim3 grid(NX, NM_CHUNKS, 2 * BATCH);  // (4, 16, 16) = 1024 blocks: one wave
    dir_max_kernel<<<grid, THREADS>>>(f, f_);

    stage2_kernel<<<S2_BLOCKS, S2_THREADS>>>(f, f_, out);  // 8192 threads, 128 blocks
}